// round 16
// baseline (speedup 1.0000x reference)
#include <cuda_runtime.h>
#include <cuda_bf16.h>
#include <math.h>
#include <stdint.h>

#define NUSERS 20000
#define NITEMS 30000
#define NTOT   50000
#define NCLUST 100
#define EMAX   500000
#define GK     1216
#define NKT    38            // GK/32
#define NPART  8             // pooling partial buffers

// ------------------------- scratch (device globals) -------------------------
__device__ float g_h[NITEMS*128];
__device__ float g_X[NTOT*64];
__device__ float g_xw[NTOT*64];
__device__ float g_Xc[NTOT*64];
__device__ float g_Xcomb[NTOT*64];
__device__ float g_xh[(size_t)NTOT*128];
__device__ float g_gbuf[NTOT*64];
__device__ float g_asrc[NTOT*2];
__device__ float g_adst[NTOT*2];
__device__ float g_dinv[NTOT];
__device__ int   g_indeg[NTOT];
__device__ int   g_rowptr[NTOT+1];
__device__ int   g_cursor[NTOT];
__device__ int   g_perm[EMAX];
__device__ int   g_srcp[EMAX];
__device__ float g_eap[2*EMAX];
__device__ float g_alb[2*EMAX];
__device__ int   g_clflag[NCLUST];
__device__ float g_poolsum[NPART*NCLUST*64];
__device__ float g_poolcnt[NPART*NCLUST];
__device__ float g_pooled[NCLUST*64];
__device__ float g_xhc[NCLUST*256];
__device__ float g_acs[NCLUST*4];
__device__ float g_acd[NCLUST*4];
__device__ float g_Wd[NCLUST*4*NCLUST];
__device__ float g_clupd[NCLUST*64];
__device__ float g_esum[4];
__device__ float g_mvec[16];
__device__ float g_part1[64*64];
__device__ float g_part2[64*64];
__device__ float    g_csU[4];
__device__ unsigned g_cgeU[4];
__device__ unsigned g_geU[4];   // full-graph per (layer,head) max edge term
__device__ unsigned g_nsU[4];   // full-graph per (layer,head) max asrc
__device__ __nv_bfloat16 g_wtile[(size_t)NKT*10240];

// ------------------------- helpers -------------------------
__device__ __forceinline__ float lrelu(float x){ return x>0.f ? x : 0.2f*x; }
__device__ __forceinline__ unsigned encf(float f){
    unsigned u=__float_as_uint(f);
    return (u&0x80000000u) ? ~u : (u|0x80000000u);
}
__device__ __forceinline__ float decf(unsigned e){
    return (e&0x80000000u) ? __uint_as_float(e&0x7FFFFFFFu) : __uint_as_float(~e);
}
__device__ __forceinline__ void fma2(unsigned long long &d, unsigned long long a, unsigned long long b){
    asm("fma.rn.f32x2 %0, %1, %2, %0;" : "+l"(d) : "l"(a), "l"(b));
}
__device__ __forceinline__ unsigned long long pack2(float lo, float hi){
    unsigned long long r;
    asm("mov.b64 %0, {%1,%2};" : "=l"(r) : "f"(lo), "f"(hi));
    return r;
}
__device__ __forceinline__ float2 unpack2(unsigned long long v){
    float2 r;
    asm("mov.b64 {%0,%1}, %2;" : "=f"(r.x), "=f"(r.y) : "l"(v));
    return r;
}
__device__ __forceinline__ void mma_bf16(float* c, const uint32_t* a, const uint32_t* b){
    asm volatile("mma.sync.aligned.m16n8k16.row.col.f32.bf16.bf16.f32 "
        "{%0,%1,%2,%3}, {%4,%5,%6,%7}, {%8,%9}, {%0,%1,%2,%3};"
        : "+f"(c[0]),"+f"(c[1]),"+f"(c[2]),"+f"(c[3])
        : "r"(a[0]),"r"(a[1]),"r"(a[2]),"r"(a[3]), "r"(b[0]),"r"(b[1]));
}
__device__ __forceinline__ void split2(float2 v, uint32_t& hi, uint32_t& lo){
    __nv_bfloat162 h=__floats2bfloat162_rn(v.x, v.y);
    float2 hf=__bfloat1622float2(h);
    __nv_bfloat162 l=__floats2bfloat162_rn(v.x-hf.x, v.y-hf.y);
    hi=*reinterpret_cast<uint32_t*>(&h);
    lo=*reinterpret_cast<uint32_t*>(&l);
}
__device__ __forceinline__ void mbar_init(uint32_t mb, int cnt){
    asm volatile("mbarrier.init.shared.b64 [%0], %1;" :: "r"(mb), "r"(cnt) : "memory");
}
__device__ __forceinline__ void mbar_expect_tx(uint32_t mb, int bytes){
    asm volatile("mbarrier.arrive.expect_tx.shared.b64 _, [%0], %1;" :: "r"(mb), "r"(bytes) : "memory");
}
__device__ __forceinline__ void bulk_ld(uint32_t dst, const void* src, int bytes, uint32_t mb){
    asm volatile("cp.async.bulk.shared::cluster.global.mbarrier::complete_tx::bytes [%0], [%1], %2, [%3];"
                 :: "r"(dst), "l"(src), "r"(bytes), "r"(mb) : "memory");
}
__device__ __forceinline__ void mbar_wait(uint32_t mb, int phase){
    asm volatile(
        "{\n\t.reg .pred P;\n\t"
        "WAITL%=:\n\t"
        "mbarrier.try_wait.parity.acquire.cta.shared::cta.b64 P, [%0], %1;\n\t"
        "@!P bra WAITL%=;\n\t}"
        :: "r"(mb), "r"(phase) : "memory");
}

// ------------------------- W pre-pack (per-k-tile contiguous, smem layout) --
__global__ void pack_w(const float* __restrict__ W){   // W[k*128+n]
    int i=blockIdx.x*blockDim.x+threadIdx.x;
    if(i>=NKT*128*32) return;
    int kt=i/(128*32);
    int r=i%(128*32);
    int n=r>>5, kk=r&31;
    float w=W[(size_t)(kt*32+kk)*128+n];
    __nv_bfloat16 hi=__float2bfloat16(w);
    float rem=w-__bfloat162float(hi);
    size_t base=(size_t)kt*10240;
    g_wtile[base + n*40 + kk]        = hi;
    g_wtile[base + 5120 + n*40 + kk] = __float2bfloat16(rem);
}

// ------------------------- tensor-core fusion GEMM1 -------------------------
// A via LDG.128 double-buffered through registers + STS; B via 20KB bulk+mbar.
#define TCSTAGES 3
#define AF_FLOATS (128*36)
#define AF_BYTES  (AF_FLOATS*4)          // 18432
#define BT_BYTES  20480
#define MBAR_OFF  (TCSTAGES*(AF_BYTES+BT_BYTES))   // 116736
#define TC_SMEM   (MBAR_OFF+64)

__global__ __launch_bounds__(512)
void gemm_tc(const float* __restrict__ A1,
             const float* __restrict__ A2,
             const float* __restrict__ bias,
             float* __restrict__ out, int nrows)
{
    extern __shared__ char dynsmem[];
    const uint32_t smem_u32=(uint32_t)__cvta_generic_to_shared(dynsmem);
    const uint32_t bt_addr=smem_u32+TCSTAGES*AF_BYTES;
    const uint32_t mb_addr=smem_u32+MBAR_OFF;
    float* AfBase=(float*)dynsmem;
    const __nv_bfloat16* BtBase=(const __nv_bfloat16*)(dynsmem+TCSTAGES*AF_BYTES);

    const int tid=threadIdx.x, wid=tid>>5, lane=tid&31;
    const int wm=wid>>2, wn=wid&3;
    const int g=lane>>2, tg=lane&3;
    const int rowbase=blockIdx.x*128;

    // per-thread A mapping (2 float4 per tile)
    const int r0i=tid>>3, kq0=(tid&7)*4;
    const int r1i=(tid+512)>>3, kq1=((tid+512)&7)*4;
    const int grow0=rowbase+r0i, grow1=rowbase+r1i;
    const bool v0ok=(grow0<nrows), v1ok=(grow1<nrows);

    if(tid==0){
        #pragma unroll
        for(int s=0;s<TCSTAGES;s++) mbar_init(mb_addr+s*8, 1);
    }
    __syncthreads();

    float acc[2][4][4];
    #pragma unroll
    for(int a=0;a<2;a++)
        #pragma unroll
        for(int b=0;b<4;b++)
            #pragma unroll
            for(int c=0;c<4;c++) acc[a][b][c]=0.f;

    float4 ra0, ra1;   // pending A tile registers
    auto ldgA=[&](int kt){
        const int k0=kt*32;
        ra0=make_float4(0.f,0.f,0.f,0.f);
        ra1=make_float4(0.f,0.f,0.f,0.f);
        if(k0<64){
            if(v0ok) ra0=*(const float4*)&A1[(size_t)grow0*64+k0+kq0];
            if(v1ok) ra1=*(const float4*)&A1[(size_t)grow1*64+k0+kq1];
        } else {
            if(v0ok) ra0=*(const float4*)&A2[(size_t)grow0*1152+(k0-64)+kq0];
            if(v1ok) ra1=*(const float4*)&A2[(size_t)grow1*1152+(k0-64)+kq1];
        }
    };
    auto stsA=[&](int slot){
        float* dst=AfBase + slot*AF_FLOATS;
        *(float4*)&dst[r0i*36+kq0]=ra0;
        *(float4*)&dst[r1i*36+kq1]=ra1;
    };
    auto issueB=[&](int kt, int slot){
        if(tid==0){
            uint32_t mb=mb_addr+slot*8;
            mbar_expect_tx(mb, BT_BYTES);
            bulk_ld(bt_addr + slot*BT_BYTES, &g_wtile[(size_t)kt*10240], BT_BYTES, mb);
        }
    };

    // prologue: tile0 in smem, tile1 pending in regs, B bulks 0 & 1 in flight
    ldgA(0); stsA(0); issueB(0,0);
    ldgA(1);          issueB(1,1);

    #pragma unroll 1
    for(int t=0;t<NKT;t++){
        const int slot=t%TCSTAGES;
        // store pending tile t+1 into slot (t+1)%3 (last read at compute(t-2))
        if(t+1<NKT) stsA((t+1)%TCSTAGES);
        // start fetch of tile t+2 (regs) + its B bulk into slot (t+2)%3
        if(t+2<NKT){ issueB(t+2,(t+2)%TCSTAGES); ldgA(t+2); }

        mbar_wait(mb_addr+slot*8, (t/TCSTAGES)&1);
        __syncthreads();

        const float* AfS=AfBase + slot*AF_FLOATS;
        const __nv_bfloat16* BhS=BtBase + (size_t)slot*10240;
        const __nv_bfloat16* BlS=BhS + 5120;

        #pragma unroll
        for(int kh=0;kh<2;kh++){
            const int kb=kh*16;
            uint32_t AHf[2][4], ALf[2][4];
            #pragma unroll
            for(int mt=0;mt<2;mt++){
                int row=wm*32+mt*16+g;
                float2 v0=*(const float2*)&AfS[row*36+kb+tg*2];
                float2 v1=*(const float2*)&AfS[(row+8)*36+kb+tg*2];
                float2 v2=*(const float2*)&AfS[row*36+kb+8+tg*2];
                float2 v3=*(const float2*)&AfS[(row+8)*36+kb+8+tg*2];
                split2(v0,AHf[mt][0],ALf[mt][0]);
                split2(v1,AHf[mt][1],ALf[mt][1]);
                split2(v2,AHf[mt][2],ALf[mt][2]);
                split2(v3,AHf[mt][3],ALf[mt][3]);
            }
            #pragma unroll
            for(int nt=0;nt<4;nt++){
                int n=wn*32+nt*8+g;
                uint32_t bh[2], bl[2];
                bh[0]=*(const uint32_t*)&BhS[n*40+kb+tg*2];
                bh[1]=*(const uint32_t*)&BhS[n*40+kb+8+tg*2];
                bl[0]=*(const uint32_t*)&BlS[n*40+kb+tg*2];
                bl[1]=*(const uint32_t*)&BlS[n*40+kb+8+tg*2];
                #pragma unroll
                for(int mt=0;mt<2;mt++){
                    mma_bf16(acc[mt][nt], AHf[mt], bh);
                    mma_bf16(acc[mt][nt], AHf[mt], bl);
                    mma_bf16(acc[mt][nt], ALf[mt], bh);
                }
            }
        }
        __syncthreads();
    }

    #pragma unroll
    for(int nt=0;nt<4;nt++){
        int col=wn*32+nt*8+tg*2;
        float b0=bias[col], b1=bias[col+1];
        #pragma unroll
        for(int mt=0;mt<2;mt++){
            int r=rowbase+wm*32+mt*16+g;
            if(r<nrows){
                float2 v;
                v.x=fmaxf(acc[mt][nt][0]+b0,0.f);
                v.y=fmaxf(acc[mt][nt][1]+b1,0.f);
                *(float2*)&out[(size_t)r*128+col]=v;
            }
            if(r+8<nrows){
                float2 v;
                v.x=fmaxf(acc[mt][nt][2]+b0,0.f);
                v.y=fmaxf(acc[mt][nt][3]+b1,0.f);
                *(float2*)&out[(size_t)(r+8)*128+col]=v;
            }
        }
    }
}

// ------------------------- big-tile GEMM (f32x2 FMA, double buffered) -------
template<int K, int NOUT, bool RELU, bool CONCAT>
__global__ __launch_bounds__(256,2)
void gemm_big(const float* __restrict__ A1, int lda1,
              const float* __restrict__ A2, int lda2, int ksplit,
              const float* __restrict__ W, const float* __restrict__ bias,
              float* __restrict__ out, int nrows)
{
    constexpr int BM=128, BN=NOUT, BK=8;
    constexpr int TN=BN/16;
    constexpr int NT=K/BK;
    constexpr int WF=BN/32;
    __shared__ __align__(16) float As[2][BK][BM];
    __shared__ __align__(16) float Ws[2][BK][BN];
    const int tid=threadIdx.x;
    const int tx=tid&15, ty=tid>>4;
    const int rowbase=blockIdx.x*BM;

    const int ar=tid>>1, ak=(tid&1)*4;
    const int arow=rowbase+ar;
    const bool avalid=(arow<nrows);
    const int wbase=tid*WF;
    const int wk=wbase/BN, wn=wbase%BN;

    unsigned long long acc[8][TN/2];
    #pragma unroll
    for(int i=0;i<8;i++)
        #pragma unroll
        for(int j=0;j<TN/2;j++) acc[i][j]=0ull;

    auto loadA=[&](int k)->float4{
        if(!avalid) return make_float4(0.f,0.f,0.f,0.f);
        if(!CONCAT || k<ksplit) return *(const float4*)&A1[(size_t)arow*lda1+k];
        return *(const float4*)&A2[(size_t)arow*lda2+(k-ksplit)];
    };

    {
        float4 a=loadA(ak);
        As[0][ak+0][ar]=a.x; As[0][ak+1][ar]=a.y;
        As[0][ak+2][ar]=a.z; As[0][ak+3][ar]=a.w;
        if(WF==4){
            float4 w=*(const float4*)&W[(size_t)wk*BN+wn];
            *(float4*)&Ws[0][wk][wn]=w;
        } else {
            float2 w=*(const float2*)&W[(size_t)wk*BN+wn];
            *(float2*)&Ws[0][wk][wn]=w;
        }
    }
    __syncthreads();

    float4 nA; float4 nW4; float2 nW2;
    #pragma unroll 1
    for(int t=0;t<NT;t++){
        const int cur=t&1;
        if(t+1<NT){
            int k0=(t+1)*BK;
            nA=loadA(k0+ak);
            if(WF==4) nW4=*(const float4*)&W[(size_t)(k0+wk)*BN+wn];
            else      nW2=*(const float2*)&W[(size_t)(k0+wk)*BN+wn];
        }
        #pragma unroll
        for(int k=0;k<BK;k++){
            float4 a0=*(const float4*)&As[cur][k][ty*8];
            float4 a1=*(const float4*)&As[cur][k][ty*8+4];
            unsigned long long av[8]={
                pack2(a0.x,a0.x),pack2(a0.y,a0.y),pack2(a0.z,a0.z),pack2(a0.w,a0.w),
                pack2(a1.x,a1.x),pack2(a1.y,a1.y),pack2(a1.z,a1.z),pack2(a1.w,a1.w)};
            unsigned long long bv[TN/2];
            #pragma unroll
            for(int j=0;j<TN/2;j+=2){
                float4 b=*(const float4*)&Ws[cur][k][tx*TN+j*2];
                bv[j]=pack2(b.x,b.y); bv[j+1]=pack2(b.z,b.w);
            }
            #pragma unroll
            for(int i=0;i<8;i++)
                #pragma unroll
                for(int j=0;j<TN/2;j++)
                    fma2(acc[i][j], av[i], bv[j]);
        }
        if(t+1<NT){
            __syncthreads();
            const int nxt=cur^1;
            As[nxt][ak+0][ar]=nA.x; As[nxt][ak+1][ar]=nA.y;
            As[nxt][ak+2][ar]=nA.z; As[nxt][ak+3][ar]=nA.w;
            if(WF==4) *(float4*)&Ws[nxt][wk][wn]=nW4;
            else      *(float2*)&Ws[nxt][wk][wn]=nW2;
            __syncthreads();
        }
    }

    #pragma unroll
    for(int i=0;i<8;i++){
        int r=rowbase+ty*8+i;
        if(r>=nrows) continue;
        #pragma unroll
        for(int j=0;j<TN/2;j++){
            float2 v=unpack2(acc[i][j]);
            int c=tx*TN+j*2;
            if(bias){ v.x+=bias[c]; v.y+=bias[c+1]; }
            if(RELU){ v.x=fmaxf(v.x,0.f); v.y=fmaxf(v.y,0.f); }
            out[(size_t)r*NOUT+c]  =v.x;
            out[(size_t)r*NOUT+c+1]=v.y;
        }
    }
}

// ------------------------- small generic GEMM (pooled 100x256) --------------
template<int K, int NOUT, bool RELU, bool CONCAT>
__global__ void gemm_rows(const float* __restrict__ A1, int lda1,
                          const float* __restrict__ A2, int lda2, int ksplit,
                          const float* __restrict__ W,
                          const float* __restrict__ bias,
                          float* __restrict__ out, int nrows)
{
    constexpr int BM=64, BK=16;
    constexpr int TN = NOUT/16;
    __shared__ __align__(16) float As[BK][BM];
    __shared__ __align__(16) float Ws[BK][NOUT];
    int tid=threadIdx.x;
    int tx=tid&15, ty=tid>>4;
    int rowbase=blockIdx.x*BM;
    unsigned long long acc[4][TN/2];
    #pragma unroll
    for(int i=0;i<4;i++)
        #pragma unroll
        for(int j=0;j<TN/2;j++) acc[i][j]=0ull;

    for(int k0=0;k0<K;k0+=BK){
        #pragma unroll
        for(int i=0;i<BM*BK/256;i++){
            int idx=tid+i*256;
            int r=idx>>4, kk=idx&15;
            int grow=rowbase+r, gk=k0+kk;
            float v=0.f;
            if(grow<nrows){
                if(!CONCAT || gk<ksplit) v=A1[(size_t)grow*lda1+gk];
                else v=A2[(size_t)grow*lda2+(gk-ksplit)];
            }
            As[kk][r]=v;
        }
        #pragma unroll
        for(int i=0;i<BK*NOUT/256;i++){
            int idx=tid+i*256;
            int kk=idx/NOUT, c=idx%NOUT;
            Ws[kk][c]=W[(size_t)(k0+kk)*NOUT+c];
        }
        __syncthreads();
        #pragma unroll
        for(int kk=0;kk<BK;kk++){
            float4 a4=*(const float4*)&As[kk][ty*4];
            unsigned long long av[4]={pack2(a4.x,a4.x),pack2(a4.y,a4.y),
                                      pack2(a4.z,a4.z),pack2(a4.w,a4.w)};
            unsigned long long bv[TN/2];
            #pragma unroll
            for(int j=0;j<TN/2;j+=2){
                float4 b4=*(const float4*)&Ws[kk][tx*TN+j*2];
                bv[j]=pack2(b4.x,b4.y); bv[j+1]=pack2(b4.z,b4.w);
            }
            #pragma unroll
            for(int i=0;i<4;i++)
                #pragma unroll
                for(int j=0;j<TN/2;j++)
                    fma2(acc[i][j], av[i], bv[j]);
        }
        __syncthreads();
    }
    #pragma unroll
    for(int i=0;i<4;i++){
        int r=rowbase+ty*4+i;
        if(r>=nrows) continue;
        #pragma unroll
        for(int j=0;j<TN/2;j++){
            float2 v=unpack2(acc[i][j]);
            int c=tx*TN+j*2;
            if(bias){ v.x+=bias[c]; v.y+=bias[c+1]; }
            if(RELU){ v.x=fmaxf(v.x,0.f); v.y=fmaxf(v.y,0.f); }
            out[(size_t)r*NOUT+c]  =v.x;
            out[(size_t)r*NOUT+c+1]=v.y;
        }
    }
}

// ------------------------- setup / graph build -------------------------
__global__ void zero_scratch(const float* __restrict__ user_emb){
    int i=blockIdx.x*blockDim.x+threadIdx.x;
    int stride=gridDim.x*blockDim.x;
    for(int k=i;k<NTOT;k+=stride) g_indeg[k]=0;
    for(int k=i;k<NCLUST*4*NCLUST;k+=stride) g_Wd[k]=0.f;
    for(int k=i;k<NPART*NCLUST*64;k+=stride) g_poolsum[k]=0.f;
    for(int k=i;k<NPART*NCLUST;k+=stride) g_poolcnt[k]=0.f;
    for(int k=i;k<NCLUST;k+=stride) g_clflag[k]=0;
    if(i<4){
        g_esum[i]=0.f;
        g_cgeU[i]=encf(-3.0e38f);
        g_geU[i]=encf(-3.0e38f);
        g_nsU[i]=encf(-3.0e38f);
    }
    const float4* u4=(const float4*)user_emb;
    float4* x4=(float4*)g_X;
    for(int k=i;k<NUSERS*16;k+=stride) x4[k]=u4[k];
}

__global__ void setup_coeffs(const float* __restrict__ cg_le, const float* __restrict__ cg_ae,
                             const float* __restrict__ g_le, const float* __restrict__ g_ae){
    int t=threadIdx.x;
    if(t<8){
        int h=t>>1, k=t&1;
        float s=0.f;
        for(int c=0;c<64;c++) s+=cg_le[k*256+h*64+c]*cg_ae[h*64+c];
        g_mvec[t]=s;
    } else if(t<16){
        int q=t-8; int i=q>>2, h=(q>>1)&1, k=q&1;
        float s=0.f;
        for(int c=0;c<64;c++) s+=g_le[i*256+k*128+h*64+c]*g_ae[i*128+h*64+c];
        g_mvec[t]=s;
    }
}

__global__ void hist_kernel(const int* __restrict__ dst, int E){
    int e=blockIdx.x*blockDim.x+threadIdx.x;
    if(e<E) atomicAdd(&g_indeg[dst[e]], 1);
}

__global__ void scan_kernel(){
    __shared__ int wsum[32];
    __shared__ int carry;
    int tid=threadIdx.x;
    if(tid==0) carry=0;
    __syncthreads();
    for(int base=0;base<NTOT;base+=1024){
        int i=base+tid;
        int v=(i<NTOT)?g_indeg[i]:0;
        int x=v;
        #pragma unroll
        for(int o=1;o<32;o<<=1){int y=__shfl_up_sync(0xffffffffu,x,o); if((tid&31)>=o)x+=y;}
        if((tid&31)==31) wsum[tid>>5]=x;
        __syncthreads();
        if(tid<32){
            int w=wsum[tid];
            #pragma unroll
            for(int o=1;o<32;o<<=1){int y=__shfl_up_sync(0xffffffffu,w,o); if(tid>=o)w+=y;}
            wsum[tid]=w;
        }
        __syncthreads();
        int off=(tid>=32)?wsum[(tid>>5)-1]:0;
        int excl=x-v+off+carry;
        if(i<NTOT){ g_rowptr[i]=excl; g_cursor[i]=excl; }
        int total=wsum[31];
        __syncthreads();
        if(tid==0) carry+=total;
        __syncthreads();
    }
    if(threadIdx.x==0) g_rowptr[NTOT]=carry;
}

__global__ void scatter_kernel(const int* __restrict__ dst, int E){
    int e=blockIdx.x*blockDim.x+threadIdx.x;
    if(e<E){
        int p=atomicAdd(&g_cursor[dst[e]],1);
        g_perm[p]=e;
    }
}

__global__ void build_perm(const int* __restrict__ src, const float* __restrict__ ea, int E){
    int j=blockIdx.x*blockDim.x+threadIdx.x;
    if(j<E){
        int e=g_perm[j];
        g_srcp[j]=src[e];
        g_eap[2*j]  =ea[2*e];
        g_eap[2*j+1]=ea[2*e+1];
    }
}

// reduce2 over fea: col sums (esum[0:2]) + per-(layer,head) max edge term g_geU
__global__ void reduce2_kernel(const float* __restrict__ a, int n, int off){
    __shared__ float s0[256], s1[256];
    __shared__ float shm[4][8];
    int tid=threadIdx.x, lane=tid&31, w=tid>>5;
    float r0=0.f, r1=0.f;
    float m[4]={-3.0e38f,-3.0e38f,-3.0e38f,-3.0e38f};
    for(int i=blockIdx.x*blockDim.x+tid;i<n;i+=gridDim.x*blockDim.x){
        float e0=a[2*i], e1=a[2*i+1];
        r0+=e0; r1+=e1;
        if(off==0){
            #pragma unroll
            for(int q=0;q<4;q++){
                int base=8+(q>>1)*4+(q&1)*2;
                m[q]=fmaxf(m[q], e0*g_mvec[base]+e1*g_mvec[base+1]);
            }
        }
    }
    s0[tid]=r0; s1[tid]=r1; __syncthreads();
    for(int o=128;o;o>>=1){
        if(tid<o){ s0[tid]+=s0[tid+o]; s1[tid]+=s1[tid+o]; }
        __syncthreads();
    }
    if(tid==0){ atomicAdd(&g_esum[off],s0[0]); atomicAdd(&g_esum[off+1],s1[0]); }
    if(off==0){
        #pragma unroll
        for(int q=0;q<4;q++){
            float v=m[q];
            #pragma unroll
            for(int o=16;o;o>>=1) v=fmaxf(v,__shfl_xor_sync(0xffffffffu,v,o));
            if(lane==0) shm[q][w]=v;
        }
        __syncthreads();
        if(tid<4){
            float v=shm[tid][0];
            #pragma unroll
            for(int qq=1;qq<8;qq++) v=fmaxf(v,shm[tid][qq]);
            atomicMax(&g_geU[tid], encf(v));
        }
    }
}

// one pass over cea: col sums (esum[2:4]) + per-head max edge term g_cgeU
__global__ void reduce_cea(const float* __restrict__ a, int n){
    __shared__ float s0[256], s1[256];
    __shared__ float shm[4][8];
    int tid=threadIdx.x, lane=tid&31, w=tid>>5;
    float r0=0.f, r1=0.f;
    float m[4]={-3.0e38f,-3.0e38f,-3.0e38f,-3.0e38f};
    for(int i=blockIdx.x*blockDim.x+tid;i<n;i+=gridDim.x*blockDim.x){
        float e0=a[2*i], e1=a[2*i+1];
        r0+=e0; r1+=e1;
        #pragma unroll
        for(int h=0;h<4;h++)
            m[h]=fmaxf(m[h], e0*g_mvec[h*2]+e1*g_mvec[h*2+1]);
    }
    s0[tid]=r0; s1[tid]=r1; __syncthreads();
    for(int o=128;o;o>>=1){
        if(tid<o){ s0[tid]+=s0[tid+o]; s1[tid]+=s1[tid+o]; }
        __syncthreads();
    }
    if(tid==0){ atomicAdd(&g_esum[2],s0[0]); atomicAdd(&g_esum[3],s1[0]); }
    #pragma unroll
    for(int h=0;h<4;h++){
        float v=m[h];
        #pragma unroll
        for(int o=16;o;o>>=1) v=fmaxf(v,__shfl_xor_sync(0xffffffffu,v,o));
        if(lane==0) shm[h][w]=v;
    }
    __syncthreads();
    if(tid<4){
        float v=shm[tid][0];
        #pragma unroll
        for(int q=1;q<8;q++) v=fmaxf(v,shm[tid][q]);
        atomicMax(&g_cgeU[tid], encf(v));
    }
}

// ------------------------- GCN -------------------------
__global__ void gcn_deg(const int* __restrict__ ca){
    int n=blockIdx.x*blockDim.x+threadIdx.x;
    if(n>=NTOT) return;
    int c=ca[n];
    int cnt=1, found=0;
    int je=g_rowptr[n+1];
    for(int j=g_rowptr[n];j<je;j++){
        if(ca[g_srcp[j]]==c){ cnt++; found=1; }
    }
    g_dinv[n]=rsqrtf((float)cnt);
    if(found) g_clflag[c]=1;
}

__global__ void gcn_agg_kernel(const int* __restrict__ ca, const float* __restrict__ gcn_b){
    int warp=(blockIdx.x*blockDim.x+threadIdx.x)>>5;
    int lane=threadIdx.x&31;
    if(warp>=NTOT) return;
    int n=warp;
    int c=ca[n];
    int part=blockIdx.x&(NPART-1);
    float dn=g_dinv[n];
    float a0=0.f, a1=0.f;
    int js=g_rowptr[n], je=g_rowptr[n+1];
    for(int j=js;j<je;j++){
        int s=g_srcp[j];
        if(ca[s]!=c) continue;
        float w=g_dinv[s];
        a0=fmaf(g_xw[s*64+lane],   w, a0);
        a1=fmaf(g_xw[s*64+lane+32],w, a1);
    }
    float r0=(a0*dn + g_xw[n*64+lane]   *dn*dn) + gcn_b[lane];
    float r1=(a1*dn + g_xw[n*64+lane+32]*dn*dn) + gcn_b[lane+32];
    if(!g_clflag[c]){ r0=g_X[n*64+lane]; r1=g_X[n*64+lane+32]; }
    g_Xc[n*64+lane]=r0; g_Xc[n*64+lane+32]=r1;
    float* psum=&g_poolsum[(size_t)(part*NCLUST+c)*64];
    atomicAdd(&psum[lane],    r0);
    atomicAdd(&psum[lane+32], r1);
    if(lane==0) atomicAdd(&g_poolcnt[part*NCLUST+c], 1.0f);
}

__global__ void pool_div(){
    int i=blockIdx.x*blockDim.x+threadIdx.x;
    if(i<NCLUST*64){
        int c=i>>6, ch=i&63;
        float s=0.f, cnt=0.f;
        #pragma unroll
        for(int p=0;p<NPART;p++){
            s+=g_poolsum[(size_t)(p*NCLUST+c)*64+ch];
            cnt+=g_poolcnt[p*NCLUST+c];
        }
        g_pooled[i]=s/fmaxf(cnt,1.0f);
    }
}

// ------------------------- cluster GAT (dense, heads=4) ---------------------
__global__ void cg_att_csmax(const float* __restrict__ as_, const float* __restrict__ ad_){
    int t=threadIdx.x;
    if(t<NCLUST*4){
        int cn=t>>2, h=t&3;
        float s=0.f, d=0.f;
        for(int c=0;c<64;c++){
            float xv=g_xhc[cn*256+h*64+c];
            s=fmaf(xv, as_[h*64+c], s);
            d=fmaf(xv, ad_[h*64+c], d);
        }
        g_acs[t]=s; g_acd[t]=d;
    }
    __syncthreads();
    if(t<128){
        int h=t>>5, lane=t&31;
        float m=-3.0e38f;
        for(int c=lane;c<NCLUST;c+=32) m=fmaxf(m, g_acs[c*4+h]);
        #pragma unroll
        for(int o=16;o;o>>=1) m=fmaxf(m,__shfl_xor_sync(0xffffffffu,m,o));
        if(lane==0) g_csU[h]=m;
    }
}

__global__ void cg_passB(const int* __restrict__ cei, const float* __restrict__ cea, int Ec){
    int e=blockIdx.x*blockDim.x+threadIdx.x;
    if(e<Ec){
        int u=cei[e], v=cei[Ec+e];
        float e0=cea[2*e], e1=cea[2*e+1];
        #pragma unroll
        for(int h=0;h<4;h++){
            float U=lrelu(g_csU[h]+g_acd[v*4+h]+decf(g_cgeU[h]));
            float al=lrelu(g_acs[u*4+h]+g_acd[v*4+h]+e0*g_mvec[h*2]+e1*g_mvec[h*2+1]);
            float ex=__expf(al - U);
            atomicAdd(&g_Wd[(v*4+h)*NCLUST+u], ex);
        }
    }
    if(e<NCLUST){
        float me0=g_esum[2]/(float)Ec, me1=g_esum[3]/(float)Ec;
        #pragma unroll
        for(int h=0;h<4;h++){
            float U=lrelu(g_csU[h]+g_acd[e*4+h]+decf(g_cgeU[h]));
            float al=lrelu(g_acs[e*4+h]+g_acd[e*4+h]+me0*g_mvec[h*2]+me1*g_mvec[h*2+1]);
            float ex=__expf(al - U);
            atomicAdd(&g_Wd[(e*4+h)*NCLUST+e], ex);
        }
    }
}

__global__ void cg_passC(const float* __restrict__ cg_bias){
    __shared__ float sh[256];
    int cdst=blockIdx.x;
    int h=threadIdx.x>>6, ch=threadIdx.x&63;
    float acc=0.f, wsum=0.f;
    const float* Wrow=&g_Wd[(cdst*4+h)*NCLUST];
    for(int s=0;s<NCLUST;s++){
        float w=Wrow[s];
        acc=fmaf(w, g_xhc[s*256+h*64+ch], acc);
        wsum+=w;
    }
    acc/= (wsum+1e-16f);
    sh[threadIdx.x]=acc;
    __syncthreads();
    if(h==0){
        float r=(sh[ch]+sh[64+ch]+sh[128+ch]+sh[192+ch])*0.25f + cg_bias[ch];
        g_clupd[cdst*64+ch]=r;
    }
}

__global__ void add_clupd(const int* __restrict__ ca){
    int i=blockIdx.x*blockDim.x+threadIdx.x;
    if(i<NTOT*64)
        g_Xcomb[i]=g_Xc[i]+g_clupd[ca[i>>6]*64+(i&63)];
}

// ------------------------- full-graph GAT -------------------------
__global__ void att_nodes(int layer, const float* __restrict__ as_, const float* __restrict__ ad_){
    __shared__ float shm[2][8];
    int t=blockIdx.x*blockDim.x+threadIdx.x;
    int lane=threadIdx.x&31, w=threadIdx.x>>5;
    float s=-3.0e38f;
    int h=t&1;
    if(t<NTOT*2){
        int n=t>>1;
        const float4* xr=(const float4*)&g_xh[(size_t)n*128+h*64];
        const float4* ar=(const float4*)&as_[h*64];
        const float4* dr=(const float4*)&ad_[h*64];
        float sv=0.f, d=0.f;
        #pragma unroll
        for(int q=0;q<16;q++){
            float4 x=xr[q], a=ar[q], b=dr[q];
            sv+=x.x*a.x+x.y*a.y+x.z*a.z+x.w*a.w;
            d+=x.x*b.x+x.y*b.y+x.z*b.z+x.w*b.w;
        }
        g_asrc[t]=sv; g_adst[t]=d;
        s=sv;
    }
    #pragma unroll
    for(int o=2;o<32;o<<=1) s=fmaxf(s,__shfl_xor_sync(0xffffffffu,s,o));
    if(lane<2) shm[lane][w]=s;
    __syncthreads();
    if(threadIdx.x<2){
        float v=shm[threadIdx.x][0];
        #pragma unroll
        for(int q=1;q<8;q++) v=fmaxf(v,shm[threadIdx.x][q]);
        atomicMax(&g_nsU[layer*2+threadIdx.x], encf(v));
    }
}

// 2-sweep GAT aggregation with global softmax shift bound U (exact math).
__global__ void gat_agg_kernel(int layer, const float* __restrict__ bias, int E){
    int warp=(blockIdx.x*blockDim.x+threadIdx.x)>>5;
    int lane=threadIdx.x&31;
    if(warp>=NTOT) return;
    int n=warp;
    float m00=g_mvec[8+layer*4+0], m01=g_mvec[8+layer*4+1];
    float m10=g_mvec[8+layer*4+2], m11=g_mvec[8+layer*4+3];
    float me0=g_esum[0]/(float)E, me1=g_esum[1]/(float)E;
    float met0=me0*m00+me1*m01, met1=me0*m10+me1*m11;
    float Ue0=fmaxf(decf(g_geU[layer*2+0]), met0);
    float Ue1=fmaxf(decf(g_geU[layer*2+1]), met1);
    float ad0=g_adst[n*2], ad1=g_adst[n*2+1];
    float U0=lrelu(decf(g_nsU[layer*2+0])+ad0+Ue0);
    float U1=lrelu(decf(g_nsU[layer*2+1])+ad1+Ue1);
    float alself0=lrelu(g_asrc[n*2]  +ad0+met0);
    float alself1=lrelu(g_asrc[n*2+1]+ad1+met1);
    int js=g_rowptr[n], je=g_rowptr[n+1];

    float ws0=__expf(alself0-U0), ws1=__expf(alself1-U1);
    float sm0=(lane==0)?ws0:0.f;
    float sm1=(lane==0)?ws1:0.f;
    for(int j=js+lane;j<je;j+=32){
        int s=g_srcp[j];
        float e0=g_eap[2*j], e1=g_eap[2*j+1];
        float w0=__expf(lrelu(g_asrc[s*2]  +ad0+e0*m00+e1*m01)-U0);
        float w1=__expf(lrelu(g_asrc[s*2+1]+ad1+e0*m10+e1*m11)-U1);
        g_alb[2*j]=w0; g_alb[2*j+1]=w1;
        sm0+=w0; sm1+=w1;
    }
    #pragma unroll
    for(int o=16;o;o>>=1){
        sm0+=__shfl_xor_sync(0xffffffffu,sm0,o);
        sm1+=__shfl_xor_sync(0xffffffffu,sm1,o);
    }
    float inv0=1.f/(sm0+1e-16f), inv1=1.f/(sm1+1e-16f);
    __threadfence_block();
    __syncwarp();

    int hsel=lane>>4;
    float invh=hsel?inv1:inv0;
    float4 acc;
    {
        float w=(hsel?ws1:ws0)*invh;
        float4 x=*(const float4*)&g_xh[(size_t)n*128+lane*4];
        acc.x=w*x.x; acc.y=w*x.y; acc.z=w*x.z; acc.w=w*x.w;
    }
    int j=js;
    for(; j+1<je; j+=2){
        int s0=g_srcp[j], s1=g_srcp[j+1];
        float w0=g_alb[2*j+hsel]*invh;
        float w1=g_alb[2*(j+1)+hsel]*invh;
        float4 x0=*(const float4*)&g_xh[(size_t)s0*128+lane*4];
        float4 x1=*(const float4*)&g_xh[(size_t)s1*128+lane*4];
        acc.x=fmaf(w0,x0.x,acc.x); acc.y=fmaf(w0,x0.y,acc.y);
        acc.z=fmaf(w0,x0.z,acc.z); acc.w=fmaf(w0,x0.w,acc.w);
        acc.x=fmaf(w1,x1.x,acc.x); acc.y=fmaf(w1,x1.y,acc.y);
        acc.z=fmaf(w1,x1.z,acc.z); acc.w=fmaf(w1,x1.w,acc.w);
    }
    if(j<je){
        int s=g_srcp[j];
        float w=g_alb[2*j+hsel]*invh;
        float4 x=*(const float4*)&g_xh[(size_t)s*128+lane*4];
        acc.x=fmaf(w,x.x,acc.x); acc.y=fmaf(w,x.y,acc.y);
        acc.z=fmaf(w,x.z,acc.z); acc.w=fmaf(w,x.w,acc.w);
    }
    float4 p;
    p.x=__shfl_down_sync(0xffffffffu,acc.x,16);
    p.y=__shfl_down_sync(0xffffffffu,acc.y,16);
    p.z=__shfl_down_sync(0xffffffffu,acc.z,16);
    p.w=__shfl_down_sync(0xffffffffu,acc.w,16);
    if(lane<16){
        int c=lane*4;
        float4 o;
        o.x=(acc.x+p.x)*0.5f+bias[c];
        o.y=(acc.y+p.y)*0.5f+bias[c+1];
        o.z=(acc.z+p.z)*0.5f+bias[c+2];
        o.w=(acc.w+p.w)*0.5f+bias[c+3];
        *(float4*)&g_gbuf[(size_t)n*64+c]=o;
    }
}

// ------------------------- GraphNorm (single-pass sum & sumsq) --------------
__global__ void gn_stats(){
    __shared__ float sh1[256], sh2[256];
    int c=threadIdx.x&63, rs=threadIdx.x>>6;
    int rows_per_blk=(NTOT+gridDim.x-1)/gridDim.x;
    int r0=blockIdx.x*rows_per_blk;
    int r1=min(r0+rows_per_blk, NTOT);
    float s1=0.f, s2=0.f;
    for(int r=r0+rs;r<r1;r+=4){
        float v=g_gbuf[(size_t)r*64+c];
        s1+=v; s2=fmaf(v,v,s2);
    }
    sh1[threadIdx.x]=s1; sh2[threadIdx.x]=s2; __syncthreads();
    if(threadIdx.x<64){
        g_part1[blockIdx.x*64+threadIdx.x]=sh1[threadIdx.x]+sh1[64+threadIdx.x]
                                          +sh1[128+threadIdx.x]+sh1[192+threadIdx.x];
        g_part2[blockIdx.x*64+threadIdx.x]=sh2[threadIdx.x]+sh2[64+threadIdx.x]
                                          +sh2[128+threadIdx.x]+sh2[192+threadIdx.x];
    }
}

__global__ void gn_final(const float* __restrict__ w, const float* __restrict__ b,
                         const float* __restrict__ ms, float* __restrict__ dst){
    __shared__ float smu[64], svar[64];
    if(threadIdx.x<64){
        float S1=0.f, S2=0.f;
        for(int bb=0;bb<64;bb++){ S1+=g_part1[bb*64+threadIdx.x]; S2+=g_part2[bb*64+threadIdx.x]; }
        float m=S1/(float)NTOT;
        float ex2=S2/(float)NTOT;
        float msv=ms[threadIdx.x];
        smu[threadIdx.x]=msv*m;
        svar[threadIdx.x]=ex2 - m*m*msv*(2.f-msv);
    }
    __syncthreads();
    for(int i=blockIdx.x*blockDim.x+threadIdx.x; i<NTOT*64; i+=gridDim.x*blockDim.x){
        int c=i&63;
        float v=g_gbuf[i]-smu[c];
        float r=w[c]*v*rsqrtf(svar[c]+1e-5f)+b[c];
        float x=r+g_Xcomb[i];
        dst[i]= x>0.f ? x : expm1f(x);
    }
}

// ------------------------- launch -------------------------
extern "C" void kernel_launch(void* const* d_in, const int* in_sizes, int n_in,
                              void* d_out, int out_size)
{
    const float* pef       =(const float*)d_in[0];
    const float* user_emb  =(const float*)d_in[1];
    const float* item_emb  =(const float*)d_in[2];
    const float* fus_w1    =(const float*)d_in[3];
    const float* fus_b1    =(const float*)d_in[4];
    const float* fus_w2    =(const float*)d_in[5];
    const float* fus_b2    =(const float*)d_in[6];
    const float* fea       =(const float*)d_in[7];
    const float* gcn_w     =(const float*)d_in[8];
    const float* gcn_b     =(const float*)d_in[9];
    const float* cg_lin    =(const float*)d_in[10];
    const float* cg_att_src=(const float*)d_in[11];
    const float* cg_att_dst=(const float*)d_in[12];
    const float* cg_lin_e  =(const float*)d_in[13];
    const float* cg_att_e  =(const float*)d_in[14];
    const float* cg_bias   =(const float*)d_in[15];
    const float* cea       =(const float*)d_in[16];
    const float* gat_lin   =(const float*)d_in[17];
    const float* gat_as    =(const float*)d_in[18];
    const float* gat_ad    =(const float*)d_in[19];
    const float* gat_le    =(const float*)d_in[20];
    const float* gat_ae    =(const float*)d_in[21];
    const float* gat_bias  =(const float*)d_in[22];
    const float* gn_w      =(const float*)d_in[23];
    const float* gn_b      =(const float*)d_in[24];
    const float* gn_ms     =(const float*)d_in[25];
    const int*   fei       =(const int*)d_in[26];
    const int*   ca        =(const int*)d_in[27];
    const int*   cei       =(const int*)d_in[28];
    int E  = in_sizes[26]/2;
    int Ec = in_sizes[28]/2;
    if(E>EMAX) E=EMAX;
    float* out=(float*)d_out;

    float *p_h,*p_X,*p_xw,*p_Xcomb,*p_xh,*p_pooled,*p_xhc;
    cudaGetSymbolAddress((void**)&p_h,      g_h);
    cudaGetSymbolAddress((void**)&p_X,      g_X);
    cudaGetSymbolAddress((void**)&p_xw,     g_xw);
    cudaGetSymbolAddress((void**)&p_Xcomb,  g_Xcomb);
    cudaGetSymbolAddress((void**)&p_xh,     g_xh);
    cudaGetSymbolAddress((void**)&p_pooled, g_pooled);
    cudaGetSymbolAddress((void**)&p_xhc,    g_xhc);

    cudaFuncSetAttribute(gemm_tc, cudaFuncAttributeMaxDynamicSharedMemorySize, TC_SMEM);

    zero_scratch<<<256,256>>>(user_emb);
    setup_coeffs<<<1,32>>>(cg_lin_e, cg_att_e, gat_le, gat_ae);
    pack_w      <<<(NKT*128*32+255)/256,256>>>(fus_w1);

    // fusion MLP
    gemm_tc<<<(NITEMS+127)/128,512,TC_SMEM>>>(item_emb, pef, fus_b1, p_h, NITEMS);
    gemm_big<128, 64, false,false><<<(NITEMS+127)/128,256>>>(p_h,128, nullptr,0,0,
                                                             fus_w2, fus_b2,
                                                             p_X+(size_t)NUSERS*64, NITEMS);

    // CSR build + edge-attr means/maxes
    hist_kernel   <<<(E+255)/256,256>>>(fei+E, E);
    scan_kernel   <<<1,1024>>>();
    scatter_kernel<<<(E+255)/256,256>>>(fei+E, E);
    build_perm    <<<(E+255)/256,256>>>(fei, fea, E);
    reduce2_kernel<<<128,256>>>(fea, E, 0);
    reduce_cea    <<<64,256>>>(cea, Ec);

    // GCN + pooling
    gemm_big<64,64,false,false><<<(NTOT+127)/128,256>>>(p_X,64, nullptr,0,0,
                                                        gcn_w, nullptr, p_xw, NTOT);
    gcn_deg       <<<(NTOT+255)/256,256>>>(ca);
    gcn_agg_kernel<<<(NTOT*32)/256,256>>>(ca, gcn_b);
    pool_div      <<<(NCLUST*64+255)/256,256>>>();

    // cluster GAT
    gemm_rows<64,256,false,false><<<(NCLUST+63)/64,256>>>(p_pooled,64, nullptr,0,0,
                                                          cg_lin, nullptr, p_xhc, NCLUST);
    cg_att_csmax<<<1,512>>>(cg_att_src, cg_att_dst);
    cg_passB<<<(Ec+255)/256,256>>>(cei, cea, Ec);
    cg_passC<<<NCLUST,256>>>(cg_bias);
    add_clupd<<<(NTOT*64+255)/256,256>>>(ca);

    // full-graph GAT stack
    for(int i=0;i<2;i++){
        gemm_big<64,128,false,false><<<(NTOT+127)/128,256>>>(p_Xcomb,64, nullptr,0,0,
                                                             gat_lin+(size_t)i*64*128,
                                                             nullptr, p_xh, NTOT);
        att_nodes     <<<(NTOT*2+255)/256,256>>>(i, gat_as+i*128, gat_ad+i*128);
        gat_agg_kernel<<<(NTOT*32)/256,256>>>(i, gat_bias+i*64, E);
        gn_stats<<<64,256>>>();
        gn_final<<<256,256>>>(gn_w+i*64, gn_b+i*64, gn_ms+i*64,
                              (i==0)?p_Xcomb:out);
    }
    (void)n_in; (void)out_size;
}

// round 17
// speedup vs baseline: 1.0340x; 1.0340x over previous
#include <cuda_runtime.h>
#include <cuda_bf16.h>
#include <math.h>
#include <stdint.h>

#define NUSERS 20000
#define NITEMS 30000
#define NTOT   50000
#define NCLUST 100
#define EMAX   500000
#define GK     1216
#define NKT    38            // GK/32
#define NPART  8             // pooling partial buffers

// ------------------------- scratch (device globals) -------------------------
__device__ float g_h[NITEMS*128];
__device__ float g_X[NTOT*64];
__device__ float g_xw[NTOT*64];
__device__ float g_Xc[NTOT*64];
__device__ float g_Xcomb[NTOT*64];
__device__ float g_xh[(size_t)NTOT*128];
__device__ float g_gbuf[NTOT*64];
__device__ float g_asrc[NTOT*2];
__device__ float g_adst[NTOT*2];
__device__ float g_dinv[NTOT];
__device__ int   g_indeg[NTOT];
__device__ int   g_rowptr[NTOT+1];
__device__ int   g_cursor[NTOT];
__device__ int   g_perm[EMAX];
__device__ int   g_srcp[EMAX];
__device__ float g_eap[2*EMAX];
__device__ float g_alb[2*EMAX];
__device__ int   g_clflag[NCLUST];
__device__ float g_poolsum[NPART*NCLUST*64];
__device__ float g_poolcnt[NPART*NCLUST];
__device__ float g_pooled[NCLUST*64];
__device__ float g_xhc[NCLUST*256];
__device__ float g_acs[NCLUST*4];
__device__ float g_acd[NCLUST*4];
__device__ float g_Wd[NCLUST*4*NCLUST];
__device__ float g_clupd[NCLUST*64];
__device__ float g_esum[4];
__device__ float g_mvec[16];
__device__ float g_part1[64*64];
__device__ float g_part2[64*64];
__device__ float    g_csU[4];
__device__ unsigned g_cgeU[4];
__device__ unsigned g_geU[4];   // full-graph per (layer,head) max edge term
__device__ unsigned g_nsU[4];   // full-graph per (layer,head) max asrc
__device__ __nv_bfloat16 g_wtile[(size_t)NKT*10240];

// ------------------------- helpers -------------------------
__device__ __forceinline__ float lrelu(float x){ return x>0.f ? x : 0.2f*x; }
__device__ __forceinline__ unsigned encf(float f){
    unsigned u=__float_as_uint(f);
    return (u&0x80000000u) ? ~u : (u|0x80000000u);
}
__device__ __forceinline__ float decf(unsigned e){
    return (e&0x80000000u) ? __uint_as_float(e&0x7FFFFFFFu) : __uint_as_float(~e);
}
__device__ __forceinline__ void fma2(unsigned long long &d, unsigned long long a, unsigned long long b){
    asm("fma.rn.f32x2 %0, %1, %2, %0;" : "+l"(d) : "l"(a), "l"(b));
}
__device__ __forceinline__ unsigned long long pack2(float lo, float hi){
    unsigned long long r;
    asm("mov.b64 %0, {%1,%2};" : "=l"(r) : "f"(lo), "f"(hi));
    return r;
}
__device__ __forceinline__ float2 unpack2(unsigned long long v){
    float2 r;
    asm("mov.b64 {%0,%1}, %2;" : "=f"(r.x), "=f"(r.y) : "l"(v));
    return r;
}
__device__ __forceinline__ void mma_bf16(float* c, const uint32_t* a, const uint32_t* b){
    asm volatile("mma.sync.aligned.m16n8k16.row.col.f32.bf16.bf16.f32 "
        "{%0,%1,%2,%3}, {%4,%5,%6,%7}, {%8,%9}, {%0,%1,%2,%3};"
        : "+f"(c[0]),"+f"(c[1]),"+f"(c[2]),"+f"(c[3])
        : "r"(a[0]),"r"(a[1]),"r"(a[2]),"r"(a[3]), "r"(b[0]),"r"(b[1]));
}
__device__ __forceinline__ void cp16(uint32_t dst, const void* src, int sz){
    asm volatile("cp.async.cg.shared.global [%0], [%1], 16, %2;"
                 :: "r"(dst), "l"(src), "r"(sz));
}
__device__ __forceinline__ void cp_commit(){ asm volatile("cp.async.commit_group;" ::: "memory"); }
__device__ __forceinline__ void split2(float2 v, uint32_t& hi, uint32_t& lo){
    __nv_bfloat162 h=__floats2bfloat162_rn(v.x, v.y);
    float2 hf=__bfloat1622float2(h);
    __nv_bfloat162 l=__floats2bfloat162_rn(v.x-hf.x, v.y-hf.y);
    hi=*reinterpret_cast<uint32_t*>(&h);
    lo=*reinterpret_cast<uint32_t*>(&l);
}
__device__ __forceinline__ void mbar_init(uint32_t mb, int cnt){
    asm volatile("mbarrier.init.shared.b64 [%0], %1;" :: "r"(mb), "r"(cnt) : "memory");
}
__device__ __forceinline__ void mbar_expect_tx(uint32_t mb, int bytes){
    asm volatile("mbarrier.arrive.expect_tx.shared.b64 _, [%0], %1;" :: "r"(mb), "r"(bytes) : "memory");
}
__device__ __forceinline__ void bulk_ld(uint32_t dst, const void* src, int bytes, uint32_t mb){
    asm volatile("cp.async.bulk.shared::cluster.global.mbarrier::complete_tx::bytes [%0], [%1], %2, [%3];"
                 :: "r"(dst), "l"(src), "r"(bytes), "r"(mb) : "memory");
}
__device__ __forceinline__ void mbar_wait(uint32_t mb, int phase){
    asm volatile(
        "{\n\t.reg .pred P;\n\t"
        "WAITL%=:\n\t"
        "mbarrier.try_wait.parity.acquire.cta.shared::cta.b64 P, [%0], %1;\n\t"
        "@!P bra WAITL%=;\n\t}"
        :: "r"(mb), "r"(phase) : "memory");
}

// ------------------------- W pre-pack (per-k-tile contiguous, smem layout) --
__global__ void pack_w(const float* __restrict__ W){   // W[k*128+n]
    int i=blockIdx.x*blockDim.x+threadIdx.x;
    if(i>=NKT*128*32) return;
    int kt=i/(128*32);
    int r=i%(128*32);
    int n=r>>5, kk=r&31;
    float w=W[(size_t)(kt*32+kk)*128+n];
    __nv_bfloat16 hi=__float2bfloat16(w);
    float rem=w-__bfloat162float(hi);
    size_t base=(size_t)kt*10240;
    g_wtile[base + n*40 + kk]        = hi;
    g_wtile[base + 5120 + n*40 + kk] = __float2bfloat16(rem);
}

// ------------------------- tensor-core fusion GEMM1 -------------------------
#define TCSTAGES 3
#define AF_FLOATS (128*36)
#define AF_BYTES  (AF_FLOATS*4)          // 18432
#define BT_BYTES  20480
#define MBAR_OFF  (TCSTAGES*(AF_BYTES+BT_BYTES))   // 116736
#define TC_SMEM   (MBAR_OFF+64)

__global__ __launch_bounds__(512)
void gemm_tc(const float* __restrict__ A1,
             const float* __restrict__ A2,
             const float* __restrict__ bias,
             float* __restrict__ out, int nrows)
{
    extern __shared__ char dynsmem[];
    const uint32_t smem_u32=(uint32_t)__cvta_generic_to_shared(dynsmem);
    const uint32_t af_addr=smem_u32;
    const uint32_t bt_addr=smem_u32+TCSTAGES*AF_BYTES;
    const uint32_t mb_addr=smem_u32+MBAR_OFF;
    float* AfBase=(float*)dynsmem;
    const __nv_bfloat16* BtBase=(const __nv_bfloat16*)(dynsmem+TCSTAGES*AF_BYTES);

    const int tid=threadIdx.x, wid=tid>>5, lane=tid&31;
    const int wm=wid>>2, wn=wid&3;
    const int g=lane>>2, tg=lane&3;
    const int rowbase=blockIdx.x*128;

    if(tid==0){
        #pragma unroll
        for(int s=0;s<TCSTAGES;s++) mbar_init(mb_addr+s*8, 1);
    }
    __syncthreads();

    float acc[2][4][4];
    #pragma unroll
    for(int a=0;a<2;a++)
        #pragma unroll
        for(int b=0;b<4;b++)
            #pragma unroll
            for(int c=0;c<4;c++) acc[a][b][c]=0.f;

    auto issue_tile=[&](int kt, int slot){
        const int k0=kt*32;
        #pragma unroll
        for(int i=0;i<2;i++){
            int idx=tid+i*512;
            int r=idx>>3, kq=idx&7;
            int grow=rowbase+r;
            const float* src;
            int sz=(grow<nrows)?16:0;
            if(k0<64) src=&A1[(size_t)grow*64 + k0 + kq*4];
            else      src=&A2[(size_t)grow*1152 + (k0-64) + kq*4];
            if(!sz) src=A1;
            cp16(af_addr + slot*AF_BYTES + (r*36+kq*4)*4, src, sz);
        }
        if(tid==0){
            uint32_t mb=mb_addr+slot*8;
            mbar_expect_tx(mb, BT_BYTES);
            bulk_ld(bt_addr + slot*BT_BYTES, &g_wtile[(size_t)kt*10240], BT_BYTES, mb);
        }
    };

    issue_tile(0,0); cp_commit();
    issue_tile(1,1); cp_commit();

    #pragma unroll 1
    for(int t=0;t<NKT;t++){
        const int slot=t%TCSTAGES;
        asm volatile("cp.async.wait_group 1;" ::: "memory");
        mbar_wait(mb_addr+slot*8, (t/TCSTAGES)&1);
        __syncthreads();

        const float* AfS=AfBase + slot*AF_FLOATS;
        const __nv_bfloat16* BhS=BtBase + (size_t)slot*10240;
        const __nv_bfloat16* BlS=BhS + 5120;

        #pragma unroll
        for(int kh=0;kh<2;kh++){
            const int kb=kh*16;
            uint32_t AHf[2][4], ALf[2][4];
            #pragma unroll
            for(int mt=0;mt<2;mt++){
                int row=wm*32+mt*16+g;
                float2 v0=*(const float2*)&AfS[row*36+kb+tg*2];
                float2 v1=*(const float2*)&AfS[(row+8)*36+kb+tg*2];
                float2 v2=*(const float2*)&AfS[row*36+kb+8+tg*2];
                float2 v3=*(const float2*)&AfS[(row+8)*36+kb+8+tg*2];
                split2(v0,AHf[mt][0],ALf[mt][0]);
                split2(v1,AHf[mt][1],ALf[mt][1]);
                split2(v2,AHf[mt][2],ALf[mt][2]);
                split2(v3,AHf[mt][3],ALf[mt][3]);
            }
            #pragma unroll
            for(int nt=0;nt<4;nt++){
                int n=wn*32+nt*8+g;
                uint32_t bh[2], bl[2];
                bh[0]=*(const uint32_t*)&BhS[n*40+kb+tg*2];
                bh[1]=*(const uint32_t*)&BhS[n*40+kb+8+tg*2];
                bl[0]=*(const uint32_t*)&BlS[n*40+kb+tg*2];
                bl[1]=*(const uint32_t*)&BlS[n*40+kb+8+tg*2];
                #pragma unroll
                for(int mt=0;mt<2;mt++){
                    mma_bf16(acc[mt][nt], AHf[mt], bh);
                    mma_bf16(acc[mt][nt], AHf[mt], bl);
                    mma_bf16(acc[mt][nt], ALf[mt], bh);
                }
            }
        }
        __syncthreads();
        if(t+2<NKT) issue_tile(t+2,(t+2)%TCSTAGES);
        cp_commit();
    }

    #pragma unroll
    for(int nt=0;nt<4;nt++){
        int col=wn*32+nt*8+tg*2;
        float b0=bias[col], b1=bias[col+1];
        #pragma unroll
        for(int mt=0;mt<2;mt++){
            int r=rowbase+wm*32+mt*16+g;
            if(r<nrows){
                float2 v;
                v.x=fmaxf(acc[mt][nt][0]+b0,0.f);
                v.y=fmaxf(acc[mt][nt][1]+b1,0.f);
                *(float2*)&out[(size_t)r*128+col]=v;
            }
            if(r+8<nrows){
                float2 v;
                v.x=fmaxf(acc[mt][nt][2]+b0,0.f);
                v.y=fmaxf(acc[mt][nt][3]+b1,0.f);
                *(float2*)&out[(size_t)(r+8)*128+col]=v;
            }
        }
    }
}

// ------------------------- big-tile GEMM (f32x2 FMA, double buffered) -------
// ATT: fused attention epilogue (NOUT=128 GAT xh GEMM): computes
// asrc/adst per (row,head) + per-head max(asrc) into g_nsU[layer*2+h].
template<int K, int NOUT, bool RELU, bool CONCAT, bool ATT>
__global__ __launch_bounds__(256,2)
void gemm_big(const float* __restrict__ A1, int lda1,
              const float* __restrict__ A2, int lda2, int ksplit,
              const float* __restrict__ W, const float* __restrict__ bias,
              float* __restrict__ out, int nrows,
              int layer, const float* __restrict__ av_s, const float* __restrict__ av_d)
{
    constexpr int BM=128, BN=NOUT, BK=8;
    constexpr int TN=BN/16;
    constexpr int NT=K/BK;
    constexpr int WF=BN/32;
    __shared__ __align__(16) float As[2][BK][BM];
    __shared__ __align__(16) float Ws[2][BK][BN];
    const int tid=threadIdx.x;
    const int tx=tid&15, ty=tid>>4;
    const int rowbase=blockIdx.x*BM;

    const int ar=tid>>1, ak=(tid&1)*4;
    const int arow=rowbase+ar;
    const bool avalid=(arow<nrows);
    const int wbase=tid*WF;
    const int wk=wbase/BN, wn=wbase%BN;

    unsigned long long acc[8][TN/2];
    #pragma unroll
    for(int i=0;i<8;i++)
        #pragma unroll
        for(int j=0;j<TN/2;j++) acc[i][j]=0ull;

    auto loadA=[&](int k)->float4{
        if(!avalid) return make_float4(0.f,0.f,0.f,0.f);
        if(!CONCAT || k<ksplit) return *(const float4*)&A1[(size_t)arow*lda1+k];
        return *(const float4*)&A2[(size_t)arow*lda2+(k-ksplit)];
    };

    {
        float4 a=loadA(ak);
        As[0][ak+0][ar]=a.x; As[0][ak+1][ar]=a.y;
        As[0][ak+2][ar]=a.z; As[0][ak+3][ar]=a.w;
        if(WF==4){
            float4 w=*(const float4*)&W[(size_t)wk*BN+wn];
            *(float4*)&Ws[0][wk][wn]=w;
        } else {
            float2 w=*(const float2*)&W[(size_t)wk*BN+wn];
            *(float2*)&Ws[0][wk][wn]=w;
        }
    }
    __syncthreads();

    float4 nA; float4 nW4; float2 nW2;
    #pragma unroll 1
    for(int t=0;t<NT;t++){
        const int cur=t&1;
        if(t+1<NT){
            int k0=(t+1)*BK;
            nA=loadA(k0+ak);
            if(WF==4) nW4=*(const float4*)&W[(size_t)(k0+wk)*BN+wn];
            else      nW2=*(const float2*)&W[(size_t)(k0+wk)*BN+wn];
        }
        #pragma unroll
        for(int k=0;k<BK;k++){
            float4 a0=*(const float4*)&As[cur][k][ty*8];
            float4 a1=*(const float4*)&As[cur][k][ty*8+4];
            unsigned long long av[8]={
                pack2(a0.x,a0.x),pack2(a0.y,a0.y),pack2(a0.z,a0.z),pack2(a0.w,a0.w),
                pack2(a1.x,a1.x),pack2(a1.y,a1.y),pack2(a1.z,a1.z),pack2(a1.w,a1.w)};
            unsigned long long bv[TN/2];
            #pragma unroll
            for(int j=0;j<TN/2;j+=2){
                float4 b=*(const float4*)&Ws[cur][k][tx*TN+j*2];
                bv[j]=pack2(b.x,b.y); bv[j+1]=pack2(b.z,b.w);
            }
            #pragma unroll
            for(int i=0;i<8;i++)
                #pragma unroll
                for(int j=0;j<TN/2;j++)
                    fma2(acc[i][j], av[i], bv[j]);
        }
        if(t+1<NT){
            __syncthreads();
            const int nxt=cur^1;
            As[nxt][ak+0][ar]=nA.x; As[nxt][ak+1][ar]=nA.y;
            As[nxt][ak+2][ar]=nA.z; As[nxt][ak+3][ar]=nA.w;
            if(WF==4) *(float4*)&Ws[nxt][wk][wn]=nW4;
            else      *(float2*)&Ws[nxt][wk][wn]=nW2;
            __syncthreads();
        }
    }

    #pragma unroll
    for(int i=0;i<8;i++){
        int r=rowbase+ty*8+i;
        if(r>=nrows) continue;
        #pragma unroll
        for(int j=0;j<TN/2;j++){
            float2 v=unpack2(acc[i][j]);
            int c=tx*TN+j*2;
            if(bias){ v.x+=bias[c]; v.y+=bias[c+1]; }
            if(RELU){ v.x=fmaxf(v.x,0.f); v.y=fmaxf(v.y,0.f); }
            out[(size_t)r*NOUT+c]  =v.x;
            out[(size_t)r*NOUT+c+1]=v.y;
        }
    }

    if(ATT){
        // cols tx*8..tx*8+7 belong to head h = tx>>3; flat att layout [128]
        const int h=tx>>3;
        float avs[8], avd[8];
        #pragma unroll
        for(int j=0;j<8;j++){ avs[j]=av_s[tx*8+j]; avd[j]=av_d[tx*8+j]; }
        float smax=-3.0e38f;
        #pragma unroll
        for(int i=0;i<8;i++){
            float s=0.f, d=0.f;
            #pragma unroll
            for(int j=0;j<4;j++){
                float2 v=unpack2(acc[i][j]);
                s=fmaf(v.x,avs[j*2],s);   s=fmaf(v.y,avs[j*2+1],s);
                d=fmaf(v.x,avd[j*2],d);   d=fmaf(v.y,avd[j*2+1],d);
            }
            // reduce over 8-lane head group (lane bits 0..2 == tx bits 0..2)
            #pragma unroll
            for(int o=1;o<8;o<<=1){
                s+=__shfl_xor_sync(0xffffffffu,s,o);
                d+=__shfl_xor_sync(0xffffffffu,d,o);
            }
            int r=rowbase+ty*8+i;
            if((tx&7)==0 && r<nrows){
                g_asrc[r*2+h]=s;
                g_adst[r*2+h]=d;
                smax=fmaxf(smax,s);
            }
        }
        if((tx&7)==0) atomicMax(&g_nsU[layer*2+h], encf(smax));
    }
}

// ------------------------- small generic GEMM (pooled 100x256) --------------
template<int K, int NOUT, bool RELU, bool CONCAT>
__global__ void gemm_rows(const float* __restrict__ A1, int lda1,
                          const float* __restrict__ A2, int lda2, int ksplit,
                          const float* __restrict__ W,
                          const float* __restrict__ bias,
                          float* __restrict__ out, int nrows)
{
    constexpr int BM=64, BK=16;
    constexpr int TN = NOUT/16;
    __shared__ __align__(16) float As[BK][BM];
    __shared__ __align__(16) float Ws[BK][NOUT];
    int tid=threadIdx.x;
    int tx=tid&15, ty=tid>>4;
    int rowbase=blockIdx.x*BM;
    unsigned long long acc[4][TN/2];
    #pragma unroll
    for(int i=0;i<4;i++)
        #pragma unroll
        for(int j=0;j<TN/2;j++) acc[i][j]=0ull;

    for(int k0=0;k0<K;k0+=BK){
        #pragma unroll
        for(int i=0;i<BM*BK/256;i++){
            int idx=tid+i*256;
            int r=idx>>4, kk=idx&15;
            int grow=rowbase+r, gk=k0+kk;
            float v=0.f;
            if(grow<nrows){
                if(!CONCAT || gk<ksplit) v=A1[(size_t)grow*lda1+gk];
                else v=A2[(size_t)grow*lda2+(gk-ksplit)];
            }
            As[kk][r]=v;
        }
        #pragma unroll
        for(int i=0;i<BK*NOUT/256;i++){
            int idx=tid+i*256;
            int kk=idx/NOUT, c=idx%NOUT;
            Ws[kk][c]=W[(size_t)(k0+kk)*NOUT+c];
        }
        __syncthreads();
        #pragma unroll
        for(int kk=0;kk<BK;kk++){
            float4 a4=*(const float4*)&As[kk][ty*4];
            unsigned long long av[4]={pack2(a4.x,a4.x),pack2(a4.y,a4.y),
                                      pack2(a4.z,a4.z),pack2(a4.w,a4.w)};
            unsigned long long bv[TN/2];
            #pragma unroll
            for(int j=0;j<TN/2;j+=2){
                float4 b4=*(const float4*)&Ws[kk][tx*TN+j*2];
                bv[j]=pack2(b4.x,b4.y); bv[j+1]=pack2(b4.z,b4.w);
            }
            #pragma unroll
            for(int i=0;i<4;i++)
                #pragma unroll
                for(int j=0;j<TN/2;j++)
                    fma2(acc[i][j], av[i], bv[j]);
        }
        __syncthreads();
    }
    #pragma unroll
    for(int i=0;i<4;i++){
        int r=rowbase+ty*4+i;
        if(r>=nrows) continue;
        #pragma unroll
        for(int j=0;j<TN/2;j++){
            float2 v=unpack2(acc[i][j]);
            int c=tx*TN+j*2;
            if(bias){ v.x+=bias[c]; v.y+=bias[c+1]; }
            if(RELU){ v.x=fmaxf(v.x,0.f); v.y=fmaxf(v.y,0.f); }
            out[(size_t)r*NOUT+c]  =v.x;
            out[(size_t)r*NOUT+c+1]=v.y;
        }
    }
}

// ------------------------- setup / graph build -------------------------
__global__ void zero_scratch(const float* __restrict__ user_emb){
    int i=blockIdx.x*blockDim.x+threadIdx.x;
    int stride=gridDim.x*blockDim.x;
    for(int k=i;k<NTOT;k+=stride) g_indeg[k]=0;
    for(int k=i;k<NCLUST*4*NCLUST;k+=stride) g_Wd[k]=0.f;
    for(int k=i;k<NPART*NCLUST*64;k+=stride) g_poolsum[k]=0.f;
    for(int k=i;k<NPART*NCLUST;k+=stride) g_poolcnt[k]=0.f;
    for(int k=i;k<NCLUST;k+=stride) g_clflag[k]=0;
    if(i<4){
        g_esum[i]=0.f;
        g_cgeU[i]=encf(-3.0e38f);
        g_geU[i]=encf(-3.0e38f);
        g_nsU[i]=encf(-3.0e38f);
    }
    const float4* u4=(const float4*)user_emb;
    float4* x4=(float4*)g_X;
    for(int k=i;k<NUSERS*16;k+=stride) x4[k]=u4[k];
}

__global__ void setup_coeffs(const float* __restrict__ cg_le, const float* __restrict__ cg_ae,
                             const float* __restrict__ g_le, const float* __restrict__ g_ae){
    int t=threadIdx.x;
    if(t<8){
        int h=t>>1, k=t&1;
        float s=0.f;
        for(int c=0;c<64;c++) s+=cg_le[k*256+h*64+c]*cg_ae[h*64+c];
        g_mvec[t]=s;
    } else if(t<16){
        int q=t-8; int i=q>>2, h=(q>>1)&1, k=q&1;
        float s=0.f;
        for(int c=0;c<64;c++) s+=g_le[i*256+k*128+h*64+c]*g_ae[i*128+h*64+c];
        g_mvec[t]=s;
    }
}

__global__ void hist_kernel(const int* __restrict__ dst, int E){
    int e=blockIdx.x*blockDim.x+threadIdx.x;
    if(e<E) atomicAdd(&g_indeg[dst[e]], 1);
}

__global__ void scan_kernel(){
    __shared__ int wsum[32];
    __shared__ int carry;
    int tid=threadIdx.x;
    if(tid==0) carry=0;
    __syncthreads();
    for(int base=0;base<NTOT;base+=1024){
        int i=base+tid;
        int v=(i<NTOT)?g_indeg[i]:0;
        int x=v;
        #pragma unroll
        for(int o=1;o<32;o<<=1){int y=__shfl_up_sync(0xffffffffu,x,o); if((tid&31)>=o)x+=y;}
        if((tid&31)==31) wsum[tid>>5]=x;
        __syncthreads();
        if(tid<32){
            int w=wsum[tid];
            #pragma unroll
            for(int o=1;o<32;o<<=1){int y=__shfl_up_sync(0xffffffffu,w,o); if(tid>=o)w+=y;}
            wsum[tid]=w;
        }
        __syncthreads();
        int off=(tid>=32)?wsum[(tid>>5)-1]:0;
        int excl=x-v+off+carry;
        if(i<NTOT){ g_rowptr[i]=excl; g_cursor[i]=excl; }
        int total=wsum[31];
        __syncthreads();
        if(tid==0) carry+=total;
        __syncthreads();
    }
    if(threadIdx.x==0) g_rowptr[NTOT]=carry;
}

__global__ void scatter_kernel(const int* __restrict__ dst, int E){
    int e=blockIdx.x*blockDim.x+threadIdx.x;
    if(e<E){
        int p=atomicAdd(&g_cursor[dst[e]],1);
        g_perm[p]=e;
    }
}

__global__ void build_perm(const int* __restrict__ src, const float* __restrict__ ea, int E){
    int j=blockIdx.x*blockDim.x+threadIdx.x;
    if(j<E){
        int e=g_perm[j];
        g_srcp[j]=src[e];
        g_eap[2*j]  =ea[2*e];
        g_eap[2*j+1]=ea[2*e+1];
    }
}

// reduce2 over fea: col sums (esum[0:2]) + per-(layer,head) max edge term g_geU
__global__ void reduce2_kernel(const float* __restrict__ a, int n, int off){
    __shared__ float s0[256], s1[256];
    __shared__ float shm[4][8];
    int tid=threadIdx.x, lane=tid&31, w=tid>>5;
    float r0=0.f, r1=0.f;
    float m[4]={-3.0e38f,-3.0e38f,-3.0e38f,-3.0e38f};
    for(int i=blockIdx.x*blockDim.x+tid;i<n;i+=gridDim.x*blockDim.x){
        float e0=a[2*i], e1=a[2*i+1];
        r0+=e0; r1+=e1;
        if(off==0){
            #pragma unroll
            for(int q=0;q<4;q++){
                int base=8+(q>>1)*4+(q&1)*2;
                m[q]=fmaxf(m[q], e0*g_mvec[base]+e1*g_mvec[base+1]);
            }
        }
    }
    s0[tid]=r0; s1[tid]=r1; __syncthreads();
    for(int o=128;o;o>>=1){
        if(tid<o){ s0[tid]+=s0[tid+o]; s1[tid]+=s1[tid+o]; }
        __syncthreads();
    }
    if(tid==0){ atomicAdd(&g_esum[off],s0[0]); atomicAdd(&g_esum[off+1],s1[0]); }
    if(off==0){
        #pragma unroll
        for(int q=0;q<4;q++){
            float v=m[q];
            #pragma unroll
            for(int o=16;o;o>>=1) v=fmaxf(v,__shfl_xor_sync(0xffffffffu,v,o));
            if(lane==0) shm[q][w]=v;
        }
        __syncthreads();
        if(tid<4){
            float v=shm[tid][0];
            #pragma unroll
            for(int qq=1;qq<8;qq++) v=fmaxf(v,shm[tid][qq]);
            atomicMax(&g_geU[tid], encf(v));
        }
    }
}

// one pass over cea: col sums (esum[2:4]) + per-head max edge term g_cgeU
__global__ void reduce_cea(const float* __restrict__ a, int n){
    __shared__ float s0[256], s1[256];
    __shared__ float shm[4][8];
    int tid=threadIdx.x, lane=tid&31, w=tid>>5;
    float r0=0.f, r1=0.f;
    float m[4]={-3.0e38f,-3.0e38f,-3.0e38f,-3.0e38f};
    for(int i=blockIdx.x*blockDim.x+tid;i<n;i+=gridDim.x*blockDim.x){
        float e0=a[2*i], e1=a[2*i+1];
        r0+=e0; r1+=e1;
        #pragma unroll
        for(int h=0;h<4;h++)
            m[h]=fmaxf(m[h], e0*g_mvec[h*2]+e1*g_mvec[h*2+1]);
    }
    s0[tid]=r0; s1[tid]=r1; __syncthreads();
    for(int o=128;o;o>>=1){
        if(tid<o){ s0[tid]+=s0[tid+o]; s1[tid]+=s1[tid+o]; }
        __syncthreads();
    }
    if(tid==0){ atomicAdd(&g_esum[2],s0[0]); atomicAdd(&g_esum[3],s1[0]); }
    #pragma unroll
    for(int h=0;h<4;h++){
        float v=m[h];
        #pragma unroll
        for(int o=16;o;o>>=1) v=fmaxf(v,__shfl_xor_sync(0xffffffffu,v,o));
        if(lane==0) shm[h][w]=v;
    }
    __syncthreads();
    if(tid<4){
        float v=shm[tid][0];
        #pragma unroll
        for(int q=1;q<8;q++) v=fmaxf(v,shm[tid][q]);
        atomicMax(&g_cgeU[tid], encf(v));
    }
}

// ------------------------- GCN -------------------------
__global__ void gcn_deg(const int* __restrict__ ca){
    int n=blockIdx.x*blockDim.x+threadIdx.x;
    if(n>=NTOT) return;
    int c=ca[n];
    int cnt=1, found=0;
    int je=g_rowptr[n+1];
    for(int j=g_rowptr[n];j<je;j++){
        if(ca[g_srcp[j]]==c){ cnt++; found=1; }
    }
    g_dinv[n]=rsqrtf((float)cnt);
    if(found) g_clflag[c]=1;
}

__global__ void gcn_agg_kernel(const int* __restrict__ ca, const float* __restrict__ gcn_b){
    int warp=(blockIdx.x*blockDim.x+threadIdx.x)>>5;
    int lane=threadIdx.x&31;
    if(warp>=NTOT) return;
    int n=warp;
    int c=ca[n];
    int part=blockIdx.x&(NPART-1);
    float dn=g_dinv[n];
    float a0=0.f, a1=0.f;
    int js=g_rowptr[n], je=g_rowptr[n+1];
    for(int j=js;j<je;j++){
        int s=g_srcp[j];
        if(ca[s]!=c) continue;
        float w=g_dinv[s];
        a0=fmaf(g_xw[s*64+lane],   w, a0);
        a1=fmaf(g_xw[s*64+lane+32],w, a1);
    }
    float r0=(a0*dn + g_xw[n*64+lane]   *dn*dn) + gcn_b[lane];
    float r1=(a1*dn + g_xw[n*64+lane+32]*dn*dn) + gcn_b[lane+32];
    if(!g_clflag[c]){ r0=g_X[n*64+lane]; r1=g_X[n*64+lane+32]; }
    g_Xc[n*64+lane]=r0; g_Xc[n*64+lane+32]=r1;
    float* psum=&g_poolsum[(size_t)(part*NCLUST+c)*64];
    atomicAdd(&psum[lane],    r0);
    atomicAdd(&psum[lane+32], r1);
    if(lane==0) atomicAdd(&g_poolcnt[part*NCLUST+c], 1.0f);
}

__global__ void pool_div(){
    int i=blockIdx.x*blockDim.x+threadIdx.x;
    if(i<NCLUST*64){
        int c=i>>6, ch=i&63;
        float s=0.f, cnt=0.f;
        #pragma unroll
        for(int p=0;p<NPART;p++){
            s+=g_poolsum[(size_t)(p*NCLUST+c)*64+ch];
            cnt+=g_poolcnt[p*NCLUST+c];
        }
        g_pooled[i]=s/fmaxf(cnt,1.0f);
    }
}

// ------------------------- cluster GAT (dense, heads=4) ---------------------
__global__ void cg_att_csmax(const float* __restrict__ as_, const float* __restrict__ ad_){
    int t=threadIdx.x;
    if(t<NCLUST*4){
        int cn=t>>2, h=t&3;
        float s=0.f, d=0.f;
        for(int c=0;c<64;c++){
            float xv=g_xhc[cn*256+h*64+c];
            s=fmaf(xv, as_[h*64+c], s);
            d=fmaf(xv, ad_[h*64+c], d);
        }
        g_acs[t]=s; g_acd[t]=d;
    }
    __syncthreads();
    if(t<128){
        int h=t>>5, lane=t&31;
        float m=-3.0e38f;
        for(int c=lane;c<NCLUST;c+=32) m=fmaxf(m, g_acs[c*4+h]);
        #pragma unroll
        for(int o=16;o;o>>=1) m=fmaxf(m,__shfl_xor_sync(0xffffffffu,m,o));
        if(lane==0) g_csU[h]=m;
    }
}

__global__ void cg_passB(const int* __restrict__ cei, const float* __restrict__ cea, int Ec){
    int e=blockIdx.x*blockDim.x+threadIdx.x;
    if(e<Ec){
        int u=cei[e], v=cei[Ec+e];
        float e0=cea[2*e], e1=cea[2*e+1];
        #pragma unroll
        for(int h=0;h<4;h++){
            float U=lrelu(g_csU[h]+g_acd[v*4+h]+decf(g_cgeU[h]));
            float al=lrelu(g_acs[u*4+h]+g_acd[v*4+h]+e0*g_mvec[h*2]+e1*g_mvec[h*2+1]);
            float ex=__expf(al - U);
            atomicAdd(&g_Wd[(v*4+h)*NCLUST+u], ex);
        }
    }
    if(e<NCLUST){
        float me0=g_esum[2]/(float)Ec, me1=g_esum[3]/(float)Ec;
        #pragma unroll
        for(int h=0;h<4;h++){
            float U=lrelu(g_csU[h]+g_acd[e*4+h]+decf(g_cgeU[h]));
            float al=lrelu(g_acs[e*4+h]+g_acd[e*4+h]+me0*g_mvec[h*2]+me1*g_mvec[h*2+1]);
            float ex=__expf(al - U);
            atomicAdd(&g_Wd[(e*4+h)*NCLUST+e], ex);
        }
    }
}

__global__ void cg_passC(const float* __restrict__ cg_bias){
    __shared__ float sh[256];
    int cdst=blockIdx.x;
    int h=threadIdx.x>>6, ch=threadIdx.x&63;
    float acc=0.f, wsum=0.f;
    const float* Wrow=&g_Wd[(cdst*4+h)*NCLUST];
    for(int s=0;s<NCLUST;s++){
        float w=Wrow[s];
        acc=fmaf(w, g_xhc[s*256+h*64+ch], acc);
        wsum+=w;
    }
    acc/= (wsum+1e-16f);
    sh[threadIdx.x]=acc;
    __syncthreads();
    if(h==0){
        float r=(sh[ch]+sh[64+ch]+sh[128+ch]+sh[192+ch])*0.25f + cg_bias[ch];
        g_clupd[cdst*64+ch]=r;
    }
}

__global__ void add_clupd(const int* __restrict__ ca){
    int i=blockIdx.x*blockDim.x+threadIdx.x;
    if(i<NTOT*64)
        g_Xcomb[i]=g_Xc[i]+g_clupd[ca[i>>6]*64+(i&63)];
}

// ------------------------- full-graph GAT (2-sweep, global shift bound) -----
__global__ void gat_agg_kernel(int layer, const float* __restrict__ bias, int E){
    int warp=(blockIdx.x*blockDim.x+threadIdx.x)>>5;
    int lane=threadIdx.x&31;
    if(warp>=NTOT) return;
    int n=warp;
    float m00=g_mvec[8+layer*4+0], m01=g_mvec[8+layer*4+1];
    float m10=g_mvec[8+layer*4+2], m11=g_mvec[8+layer*4+3];
    float me0=g_esum[0]/(float)E, me1=g_esum[1]/(float)E;
    float met0=me0*m00+me1*m01, met1=me0*m10+me1*m11;
    float Ue0=fmaxf(decf(g_geU[layer*2+0]), met0);
    float Ue1=fmaxf(decf(g_geU[layer*2+1]), met1);
    float ad0=g_adst[n*2], ad1=g_adst[n*2+1];
    float U0=lrelu(decf(g_nsU[layer*2+0])+ad0+Ue0);
    float U1=lrelu(decf(g_nsU[layer*2+1])+ad1+Ue1);
    float alself0=lrelu(g_asrc[n*2]  +ad0+met0);
    float alself1=lrelu(g_asrc[n*2+1]+ad1+met1);
    int js=g_rowptr[n], je=g_rowptr[n+1];

    float ws0=__expf(alself0-U0), ws1=__expf(alself1-U1);
    float sm0=(lane==0)?ws0:0.f;
    float sm1=(lane==0)?ws1:0.f;
    for(int j=js+lane;j<je;j+=32){
        int s=g_srcp[j];
        float e0=g_eap[2*j], e1=g_eap[2*j+1];
        float w0=__expf(lrelu(g_asrc[s*2]  +ad0+e0*m00+e1*m01)-U0);
        float w1=__expf(lrelu(g_asrc[s*2+1]+ad1+e0*m10+e1*m11)-U1);
        g_alb[2*j]=w0; g_alb[2*j+1]=w1;
        sm0+=w0; sm1+=w1;
    }
    #pragma unroll
    for(int o=16;o;o>>=1){
        sm0+=__shfl_xor_sync(0xffffffffu,sm0,o);
        sm1+=__shfl_xor_sync(0xffffffffu,sm1,o);
    }
    float inv0=1.f/(sm0+1e-16f), inv1=1.f/(sm1+1e-16f);
    __threadfence_block();
    __syncwarp();

    int hsel=lane>>4;
    float invh=hsel?inv1:inv0;
    float4 acc;
    {
        float w=(hsel?ws1:ws0)*invh;
        float4 x=*(const float4*)&g_xh[(size_t)n*128+lane*4];
        acc.x=w*x.x; acc.y=w*x.y; acc.z=w*x.z; acc.w=w*x.w;
    }
    int j=js;
    for(; j+1<je; j+=2){
        int s0=g_srcp[j], s1=g_srcp[j+1];
        float w0=g_alb[2*j+hsel]*invh;
        float w1=g_alb[2*(j+1)+hsel]*invh;
        float4 x0=*(const float4*)&g_xh[(size_t)s0*128+lane*4];
        float4 x1=*(const float4*)&g_xh[(size_t)s1*128+lane*4];
        acc.x=fmaf(w0,x0.x,acc.x); acc.y=fmaf(w0,x0.y,acc.y);
        acc.z=fmaf(w0,x0.z,acc.z); acc.w=fmaf(w0,x0.w,acc.w);
        acc.x=fmaf(w1,x1.x,acc.x); acc.y=fmaf(w1,x1.y,acc.y);
        acc.z=fmaf(w1,x1.z,acc.z); acc.w=fmaf(w1,x1.w,acc.w);
    }
    if(j<je){
        int s=g_srcp[j];
        float w=g_alb[2*j+hsel]*invh;
        float4 x=*(const float4*)&g_xh[(size_t)s*128+lane*4];
        acc.x=fmaf(w,x.x,acc.x); acc.y=fmaf(w,x.y,acc.y);
        acc.z=fmaf(w,x.z,acc.z); acc.w=fmaf(w,x.w,acc.w);
    }
    float4 p;
    p.x=__shfl_down_sync(0xffffffffu,acc.x,16);
    p.y=__shfl_down_sync(0xffffffffu,acc.y,16);
    p.z=__shfl_down_sync(0xffffffffu,acc.z,16);
    p.w=__shfl_down_sync(0xffffffffu,acc.w,16);
    if(lane<16){
        int c=lane*4;
        float4 o;
        o.x=(acc.x+p.x)*0.5f+bias[c];
        o.y=(acc.y+p.y)*0.5f+bias[c+1];
        o.z=(acc.z+p.z)*0.5f+bias[c+2];
        o.w=(acc.w+p.w)*0.5f+bias[c+3];
        *(float4*)&g_gbuf[(size_t)n*64+c]=o;
    }
}

// ------------------------- GraphNorm (single-pass sum & sumsq) --------------
__global__ void gn_stats(){
    __shared__ float sh1[256], sh2[256];
    int c=threadIdx.x&63, rs=threadIdx.x>>6;
    int rows_per_blk=(NTOT+gridDim.x-1)/gridDim.x;
    int r0=blockIdx.x*rows_per_blk;
    int r1=min(r0+rows_per_blk, NTOT);
    float s1=0.f, s2=0.f;
    for(int r=r0+rs;r<r1;r+=4){
        float v=g_gbuf[(size_t)r*64+c];
        s1+=v; s2=fmaf(v,v,s2);
    }
    sh1[threadIdx.x]=s1; sh2[threadIdx.x]=s2; __syncthreads();
    if(threadIdx.x<64){
        g_part1[blockIdx.x*64+threadIdx.x]=sh1[threadIdx.x]+sh1[64+threadIdx.x]
                                          +sh1[128+threadIdx.x]+sh1[192+threadIdx.x];
        g_part2[blockIdx.x*64+threadIdx.x]=sh2[threadIdx.x]+sh2[64+threadIdx.x]
                                          +sh2[128+threadIdx.x]+sh2[192+threadIdx.x];
    }
}

__global__ void gn_final(const float* __restrict__ w, const float* __restrict__ b,
                         const float* __restrict__ ms, float* __restrict__ dst){
    __shared__ float smu[64], svar[64];
    if(threadIdx.x<64){
        float S1=0.f, S2=0.f;
        for(int bb=0;bb<64;bb++){ S1+=g_part1[bb*64+threadIdx.x]; S2+=g_part2[bb*64+threadIdx.x]; }
        float m=S1/(float)NTOT;
        float ex2=S2/(float)NTOT;
        float msv=ms[threadIdx.x];
        smu[threadIdx.x]=msv*m;
        svar[threadIdx.x]=ex2 - m*m*msv*(2.f-msv);
    }
    __syncthreads();
    for(int i=blockIdx.x*blockDim.x+threadIdx.x; i<NTOT*64; i+=gridDim.x*blockDim.x){
        int c=i&63;
        float v=g_gbuf[i]-smu[c];
        float r=w[c]*v*rsqrtf(svar[c]+1e-5f)+b[c];
        float x=r+g_Xcomb[i];
        dst[i]= x>0.f ? x : expm1f(x);
    }
}

// ------------------------- launch -------------------------
extern "C" void kernel_launch(void* const* d_in, const int* in_sizes, int n_in,
                              void* d_out, int out_size)
{
    const float* pef       =(const float*)d_in[0];
    const float* user_emb  =(const float*)d_in[1];
    const float* item_emb  =(const float*)d_in[2];
    const float* fus_w1    =(const float*)d_in[3];
    const float* fus_b1    =(const float*)d_in[4];
    const float* fus_w2    =(const float*)d_in[5];
    const float* fus_b2    =(const float*)d_in[6];
    const float* fea       =(const float*)d_in[7];
    const float* gcn_w     =(const float*)d_in[8];
    const float* gcn_b     =(const float*)d_in[9];
    const float* cg_lin    =(const float*)d_in[10];
    const float* cg_att_src=(const float*)d_in[11];
    const float* cg_att_dst=(const float*)d_in[12];
    const float* cg_lin_e  =(const float*)d_in[13];
    const float* cg_att_e  =(const float*)d_in[14];
    const float* cg_bias   =(const float*)d_in[15];
    const float* cea       =(const float*)d_in[16];
    const float* gat_lin   =(const float*)d_in[17];
    const float* gat_as    =(const float*)d_in[18];
    const float* gat_ad    =(const float*)d_in[19];
    const float* gat_le    =(const float*)d_in[20];
    const float* gat_ae    =(const float*)d_in[21];
    const float* gat_bias  =(const float*)d_in[22];
    const float* gn_w      =(const float*)d_in[23];
    const float* gn_b      =(const float*)d_in[24];
    const float* gn_ms     =(const float*)d_in[25];
    const int*   fei       =(const int*)d_in[26];
    const int*   ca        =(const int*)d_in[27];
    const int*   cei       =(const int*)d_in[28];
    int E  = in_sizes[26]/2;
    int Ec = in_sizes[28]/2;
    if(E>EMAX) E=EMAX;
    float* out=(float*)d_out;

    float *p_h,*p_X,*p_xw,*p_Xcomb,*p_xh,*p_pooled,*p_xhc;
    cudaGetSymbolAddress((void**)&p_h,      g_h);
    cudaGetSymbolAddress((void**)&p_X,      g_X);
    cudaGetSymbolAddress((void**)&p_xw,     g_xw);
    cudaGetSymbolAddress((void**)&p_Xcomb,  g_Xcomb);
    cudaGetSymbolAddress((void**)&p_xh,     g_xh);
    cudaGetSymbolAddress((void**)&p_pooled, g_pooled);
    cudaGetSymbolAddress((void**)&p_xhc,    g_xhc);

    cudaFuncSetAttribute(gemm_tc, cudaFuncAttributeMaxDynamicSharedMemorySize, TC_SMEM);

    zero_scratch<<<256,256>>>(user_emb);
    setup_coeffs<<<1,32>>>(cg_lin_e, cg_att_e, gat_le, gat_ae);
    pack_w      <<<(NKT*128*32+255)/256,256>>>(fus_w1);

    // fusion MLP
    gemm_tc<<<(NITEMS+127)/128,512,TC_SMEM>>>(item_emb, pef, fus_b1, p_h, NITEMS);
    gemm_big<128, 64, false,false,false><<<(NITEMS+127)/128,256>>>(p_h,128, nullptr,0,0,
                                                             fus_w2, fus_b2,
                                                             p_X+(size_t)NUSERS*64, NITEMS,
                                                             0, nullptr, nullptr);

    // CSR build + edge-attr means/maxes
    hist_kernel   <<<(E+255)/256,256>>>(fei+E, E);
    scan_kernel   <<<1,1024>>>();
    scatter_kernel<<<(E+255)/256,256>>>(fei+E, E);
    build_perm    <<<(E+255)/256,256>>>(fei, fea, E);
    reduce2_kernel<<<128,256>>>(fea, E, 0);
    reduce_cea    <<<64,256>>>(cea, Ec);

    // GCN + pooling
    gemm_big<64,64,false,false,false><<<(NTOT+127)/128,256>>>(p_X,64, nullptr,0,0,
                                                        gcn_w, nullptr, p_xw, NTOT,
                                                        0, nullptr, nullptr);
    gcn_deg       <<<(NTOT+255)/256,256>>>(ca);
    gcn_agg_kernel<<<(NTOT*32)/256,256>>>(ca, gcn_b);
    pool_div      <<<(NCLUST*64+255)/256,256>>>();

    // cluster GAT
    gemm_rows<64,256,false,false><<<(NCLUST+63)/64,256>>>(p_pooled,64, nullptr,0,0,
                                                          cg_lin, nullptr, p_xhc, NCLUST);
    cg_att_csmax<<<1,512>>>(cg_att_src, cg_att_dst);
    cg_passB<<<(Ec+255)/256,256>>>(cei, cea, Ec);
    cg_passC<<<NCLUST,256>>>(cg_bias);
    add_clupd<<<(NTOT*64+255)/256,256>>>(ca);

    // full-graph GAT stack (asrc/adst fused into xh GEMM epilogue)
    for(int i=0;i<2;i++){
        gemm_big<64,128,false,false,true><<<(NTOT+127)/128,256>>>(p_Xcomb,64, nullptr,0,0,
                                                             gat_lin+(size_t)i*64*128,
                                                             nullptr, p_xh, NTOT,
                                                             i, gat_as+i*128, gat_ad+i*128);
        gat_agg_kernel<<<(NTOT*32)/256,256>>>(i, gat_bias+i*64, E);
        gn_stats<<<64,256>>>();
        gn_final<<<256,256>>>(gn_w+i*64, gn_b+i*64, gn_ms+i*64,
                              (i==0)?p_Xcomb:out);
    }
    (void)n_in; (void)out_size;
}